// round 15
// baseline (speedup 1.0000x reference)
#include <cuda_runtime.h>
#include <cstdint>
#include <type_traits>

// VelocityLoss on GB300 — dual-chain cp.async pipeline with a 3-slab ring and
// ISSUE-BEFORE-COMPUTE: after each waitg, the next stage is issued before the
// arrived stage is consumed, giving every stage TWO compute intervals of
// latency cover (R14 gave one). 2 groups permanently in flight per warp.
// Slab ring (commit order A0,B0,A1,B1,...; slab = k mod 3) verified safe.
// Dynamic smem (63KB/block, 3 blocks/SM).

namespace {
constexpr int B_  = 512;
constexpr int S_  = 480;
constexpr int F_  = 149;
constexpr int VF_ = 5;
constexpr int PAIR_ROWS = 32;             // two 16-row chains per warp
constexpr int PPB = S_ / PAIR_ROWS;       // 15
constexpr int WPB = 8;                    // 256 threads
constexpr int NBLK = B_ * PPB / WPB;      // 960
constexpr int STG = 600;                  // floats per slab (2400B)
constexpr int TVF = 84;                   // floats per tv buffer (336B)
constexpr int PWF = 3 * STG + 2 * TVF;    // per-warp floats (1968)
constexpr int SMEM_BYTES = WPB * PWF * 4; // 62976
}

__device__ double g_acc[3] = {0.0, 0.0, 0.0};
__device__ unsigned int g_ticket = 0;

__constant__ int c_j[24] = {
    8, 9, 10, 11, 12, 21, 22, 23,
    0, 1, 2, 3,
    4, 5, 6, 7,
    13, 14, 15, 16,
    17, 18, 19, 20
};
__constant__ float c_wl[24] = {
    1.f/9, 1.f/9, 1.f/9, 1.f/9, 1.f/9, 1.f/9, 2.f/9, 1.f/9,
    0.1f, 0.2f, 0.3f, 0.4f,
    0.1f, 0.2f, 0.3f, 0.4f,
    0.1f, 0.2f, 0.3f, 0.4f,
    0.1f, 0.2f, 0.3f, 0.4f
};

__device__ __forceinline__ void cp16(unsigned sdst, const void* gsrc) {
    asm volatile("cp.async.cg.shared.global [%0], [%1], 16;" :: "r"(sdst), "l"(gsrc));
}
__device__ __forceinline__ void cp4(unsigned sdst, const void* gsrc) {
    asm volatile("cp.async.ca.shared.global [%0], [%1], 4;" :: "r"(sdst), "l"(gsrc));
}
__device__ __forceinline__ void commitg() { asm volatile("cp.async.commit_group;"); }
template <int N> __device__ __forceinline__ void waitg() {
    asm volatile("cp.async.wait_group %0;" :: "n"(N));
}

__global__ void __launch_bounds__(256, 3) vel_loss_ring(
    const float* __restrict__ pred,   // (B, S, F)
    const float* __restrict__ tvft,   // (B, S+1, VF)
    const float* __restrict__ meanv,  // (F,)
    const float* __restrict__ stdv,   // (F,)
    float* __restrict__ out)
{
    extern __shared__ __align__(16) float dyn[];
    __shared__ double sA[WPB], sB[WPB], sC[WPB];

    const int tid  = threadIdx.x;
    const int lane = tid & 31;
    const int warp = tid >> 5;
    const int idx  = blockIdx.x * WPB + warp;     // pair id
    const int b    = idx / PPB;
    const int pr   = idx % PPB;
    const int s0A  = pr * PAIR_ROWS;
    const int s0B  = s0A + 16;
    const unsigned FULL = 0xffffffffu;

    float* wbase = dyn + warp * PWF;
    float* slab[3] = { wbase, wbase + STG, wbase + 2 * STG };
    float* tvAp = wbase + 3 * STG;
    float* tvBp = tvAp + TVF;
    unsigned sslab[3], stvA, stvB;
    #pragma unroll
    for (int i = 0; i < 3; ++i) sslab[i] = (unsigned)__cvta_generic_to_shared(slab[i]);
    stvA = (unsigned)__cvta_generic_to_shared(tvAp);
    stvB = (unsigned)__cvta_generic_to_shared(tvBp);

    // per-lane joint parameters
    int jj = 0; float w = 0.f;
    float sp0 = 0, sp1 = 0, sp2 = 0, rv0 = 0, rv1 = 0, rv2 = 0;
    float a0c = 0, a1c = 0, a2c = 0;
    const bool act = (lane < 24);
    if (act) {
        jj = c_j[lane] * 3;
        w  = c_wl[lane];
        sp0 = stdv[jj];     sp1 = stdv[jj + 1];     sp2 = stdv[jj + 2];
        rv0 = 1.0f / stdv[72 + jj];
        rv1 = 1.0f / stdv[72 + jj + 1];
        rv2 = 1.0f / stdv[72 + jj + 2];
        a0c = meanv[72 + jj]     * rv0;
        a1c = meanv[72 + jj + 1] * rv1;
        a2c = meanv[72 + jj + 2] * rv2;
    }
    int pidx = -1;
    if      (lane == 0)  pidx = 0;
    else if (lane == 8)  pidx = 1;
    else if (lane == 12) pidx = 2;
    else if (lane == 16) pidx = 3;
    else if (lane == 20) pidx = 4;
    float mfrf = 0.f, rf = 0.f;
    if (pidx >= 0) {
        rf = 1.0f / stdv[144 + pidx];
        mfrf = meanv[144 + pidx] * rf;
    }
    const int pid0 = (pidx >= 0) ? pidx : 0;

    float accA = 0.f, accB0 = 0.f, accC = 0.f;
    float pA0 = 0.f, pA1 = 0.f, pA2 = 0.f;
    float pB0 = 0.f, pB1 = 0.f, pB2 = 0.f;

    // ---- prologue: prev-row / s==0 term (plain LDG) ----
    const bool firstA = (s0A == 0);
    const int sBegA = firstA ? 1 : s0A;
    {
        const float* rA = pred + ((size_t)(b * S_ + s0A)) * F_;
        if (firstA) {
            if (act) {
                pA0 = rA[jj]; pA1 = rA[jj + 1]; pA2 = rA[jj + 2];
                const float q0 = rA[77 + jj], q1 = rA[78 + jj], q2 = rA[79 + jj];
                accB0 = q0 * q0 + q1 * q1 + q2 * q2;
            }
        } else if (act) {
            const float* rp = rA - F_;
            pA0 = rp[jj]; pA1 = rp[jj + 1]; pA2 = rp[jj + 2];
        }
        if (act) {
            const float* rpB = pred + ((size_t)(b * S_ + s0B - 1)) * F_;
            pB0 = rpB[jj]; pB1 = rpB[jj + 1]; pB2 = rpB[jj + 2];
        }
    }

    // ---- chain-invariant loader state ----
    const uintptr_t gbA = (uintptr_t)(pred + (size_t)(b * S_ + sBegA) * F_);
    const uintptr_t gbB = (uintptr_t)(pred + (size_t)(b * S_ + s0B) * F_);
    const char* gaA = (const char*)(gbA & ~(uintptr_t)15);
    const char* gaB = (const char*)(gbB & ~(uintptr_t)15);
    const int dbA = (int)(gbA & 15), dbB = (int)(gbB & 15);
    const int dfA = dbA >> 2,        dfB = dbB >> 2;
    const int nchA = (dbA + 4 * F_ * 4 + 15) >> 4;
    const int nchB = (dbB + 4 * F_ * 4 + 15) >> 4;
    const bool lastPair = (idx == B_ * PPB - 1);

    auto loadStage = [&](const char* ga0, int nch, int sl, int t, bool useCp4) {
        const char* ga = ga0 + (size_t)t * (4 * F_ * 4);
        const unsigned sdst = sslab[sl];
        if (!useCp4) {
            #pragma unroll
            for (int i = 0; i < 5; ++i) {
                const int c = lane + i * 32;
                if (c < nch) cp16(sdst + c * 16, ga + c * 16);
            }
        } else {
            const int nw = (nch << 2) - 3;
            for (int i = lane; i < nw; i += 32)
                cp4(sdst + i * 4, ga + i * 4);
        }
        commitg();
    };

    const size_t ftvA = (size_t)(b * (S_ + 1) + sBegA) * VF_;
    const size_t ftvB = (size_t)(b * (S_ + 1) + s0B) * VF_;
    const uintptr_t gtA = (uintptr_t)(tvft + ftvA);
    const uintptr_t gtB = (uintptr_t)(tvft + ftvB);
    const int dtvA = (int)(ftvA & 3), dtvB = (int)(ftvB & 3);

    auto computeBatch = [&](int sl, int df, const float* tvp,
                            float& p0, float& p1, float& p2, auto nrc) {
        constexpr int NR = decltype(nrc)::value;
        const float* r0 = slab[sl] + df;
        float trv[NR];
        #pragma unroll
        for (int k = 0; k < NR; ++k) trv[k] = tvp[k * VF_];
        float contrib[NR];
        #pragma unroll
        for (int k = 0; k < NR; ++k) {
            contrib[k] = 0.f;
            if (act) {
                const float* rr = r0 + k * F_;
                const float c0 = rr[jj], c1 = rr[jj + 1], c2 = rr[jj + 2];
                const float q0 = rr[77 + jj], q1 = rr[78 + jj], q2 = rr[79 + jj];
                const float v0 = (c0 - p0) * sp0;
                const float v1 = (c1 - p1) * sp1;
                const float v2 = (c2 - p2) * sp2;
                const float d0 = q0 + a0c - v0 * rv0;
                const float d1 = q1 + a1c - v1 * rv1;
                const float d2 = q2 + a2c - v2 * rv2;
                accA += d0 * d0 + d1 * d1 + d2 * d2;
                contrib[k] = sqrtf(v0 * v0 + v1 * v1 + v2 * v2) * w;
                p0 = c0; p1 = c1; p2 = c2;
            }
        }
        float g4v[NR], g8v[NR];
        #pragma unroll
        for (int k = 0; k < NR; ++k) g4v[k] = contrib[k] + __shfl_xor_sync(FULL, contrib[k], 1);
        #pragma unroll
        for (int k = 0; k < NR; ++k) g4v[k] += __shfl_xor_sync(FULL, g4v[k], 2);
        #pragma unroll
        for (int k = 0; k < NR; ++k) g8v[k] = g4v[k] + __shfl_xor_sync(FULL, g4v[k], 4);
        if (pidx >= 0) {
            #pragma unroll
            for (int k = 0; k < NR; ++k) {
                const float f = (pidx == 0) ? g8v[k] : g4v[k];
                const float d = trv[k] + mfrf - f * rf;
                accC += d * d;
            }
        }
    };

    constexpr auto N4 = std::integral_constant<int, 4>{};
    constexpr auto N3 = std::integral_constant<int, 3>{};

    const float* tvpA = tvAp + dtvA + pid0;
    const float* tvpB = tvBp + dtvB + pid0;

    // ---- mainloop: 3-slab ring, issue-before-compute ----
    // commit order: A0(s0),B0(s1),A1(s2),B1(s0),A2(s1),B2(s2),A3(s0),B3(s1)
    {
        const int nchTVA = ((int)(gtA & 15) + 16 * VF_ * 4 + 15) >> 4;
        if (lane < nchTVA) cp16(stvA + lane * 16, (const char*)(gtA & ~(uintptr_t)15) + lane * 16);
    }
    loadStage(gaA, nchA, 0, 0, false);                 // group: tvA + A0
    {
        const int nchTVB = ((int)(gtB & 15) + 16 * VF_ * 4 + 15) >> 4;
        if (lane < nchTVB) cp16(stvB + lane * 16, (const char*)(gtB & ~(uintptr_t)15) + lane * 16);
    }
    loadStage(gaB, nchB, 1, 0, false);                 // group: tvB + B0

    waitg<1>(); __syncwarp();                          // A0 ready
    loadStage(gaA, nchA, 2, 1, false);                 // issue A1 first
    computeBatch(0, dfA, tvpA + 0 * VF_, pA0, pA1, pA2, N4);

    waitg<1>(); __syncwarp();                          // B0 ready
    loadStage(gaB, nchB, 0, 1, false);                 // B1 -> slab0 (A0 consumed)
    computeBatch(1, dfB, tvpB + 0 * VF_, pB0, pB1, pB2, N4);

    waitg<1>(); __syncwarp();                          // A1 ready
    loadStage(gaA, nchA, 1, 2, false);                 // A2 -> slab1 (B0 consumed)
    computeBatch(2, dfA, tvpA + 4 * VF_, pA0, pA1, pA2, N4);

    waitg<1>(); __syncwarp();                          // B1 ready
    loadStage(gaB, nchB, 2, 2, false);                 // B2 -> slab2 (A1 consumed)
    computeBatch(0, dfB, tvpB + 4 * VF_, pB0, pB1, pB2, N4);

    waitg<1>(); __syncwarp();                          // A2 ready
    loadStage(gaA, nchA, 0, 3, false);                 // A3 -> slab0 (B1 consumed)
    computeBatch(1, dfA, tvpA + 8 * VF_, pA0, pA1, pA2, N4);

    waitg<1>(); __syncwarp();                          // B2 ready
    loadStage(gaB, nchB, 1, 3, lastPair);              // B3 -> slab1 (A2 consumed)
    computeBatch(2, dfB, tvpB + 8 * VF_, pB0, pB1, pB2, N4);

    waitg<1>(); __syncwarp();                          // A3 ready
    if (!firstA) computeBatch(0, dfA, tvpA + 12 * VF_, pA0, pA1, pA2, N4);
    else         computeBatch(0, dfA, tvpA + 12 * VF_, pA0, pA1, pA2, N3);

    waitg<0>(); __syncwarp();                          // B3 ready
    computeBatch(1, dfB, tvpB + 12 * VF_, pB0, pB1, pB2, N4);

    // ---- reductions ----
    #pragma unroll
    for (int off = 16; off; off >>= 1) {
        accA  += __shfl_xor_sync(FULL, accA, off);
        accB0 += __shfl_xor_sync(FULL, accB0, off);
        accC  += __shfl_xor_sync(FULL, accC, off);
    }
    if (lane == 0) {
        sA[warp] = (double)accA;
        sB[warp] = (double)accB0;
        sC[warp] = (double)accC;
    }
    __syncthreads();

    if (warp == 0) {
        double a  = (lane < WPB) ? sA[lane] : 0.0;
        double bb = (lane < WPB) ? sB[lane] : 0.0;
        double c  = (lane < WPB) ? sC[lane] : 0.0;
        #pragma unroll
        for (int off = 4; off; off >>= 1) {
            a  += __shfl_xor_sync(FULL, a, off);
            bb += __shfl_xor_sync(FULL, bb, off);
            c  += __shfl_xor_sync(FULL, c, off);
        }
        if (lane == 0) {
            atomicAdd(&g_acc[0], a);
            atomicAdd(&g_acc[1], bb);
            atomicAdd(&g_acc[2], c);
            __threadfence();
            const unsigned t = atomicAdd(&g_ticket, 1u);
            if (t == (unsigned)(NBLK - 1)) {
                __threadfence();
                volatile double* ga = g_acc;
                const double A  = ga[0];
                const double B0 = ga[1];
                const double C  = ga[2];
                const double nA  = (double)B_ * (double)(S_ - 1) * 72.0;
                const double nB2 = (double)B_ * 72.0;
                const double nC  = (double)B_ * (double)(S_ - 1) * (double)VF_;
                const double loss1 = 10.0 * A / nA + 20.0 * B0 / nB2;
                const double loss2 = 10.0 * C / nC;
                out[0] = (float)(2.0 * loss1 + 1.5 * loss2);
                ga[0] = 0.0; ga[1] = 0.0; ga[2] = 0.0;
                g_ticket = 0;
            }
        }
    }
}

extern "C" void kernel_launch(void* const* d_in, const int* in_sizes, int n_in,
                              void* d_out, int out_size) {
    const float* pred = (const float*)d_in[0];   // predict_seq (B,S,F)
    // d_in[1] = _train_x1 (unused), d_in[2] = _train_x2 (unused)
    const float* tvft = (const float*)d_in[3];   // _true_vel_factor (B,S+1,VF)
    const float* mean = (const float*)d_in[4];   // _mean (F,)
    const float* stdv = (const float*)d_in[5];   // _std (F,)

    cudaFuncSetAttribute(vel_loss_ring,
                         cudaFuncAttributeMaxDynamicSharedMemorySize, SMEM_BYTES);
    vel_loss_ring<<<NBLK, 256, SMEM_BYTES>>>(pred, tvft, mean, stdv, (float*)d_out);
}